// round 6
// baseline (speedup 1.0000x reference)
#include <cuda_runtime.h>
#include <cuda_bf16.h>

#define Bsz 8
#define Cn  21
#define Hh  512
#define Ww  512
#define HWn (Hh * Ww)            // 262144
#define NPIX (Bsz * HWn)         // 2097152
#define LDAM_MAX_M 0.5f
#define LDAM_S     30.0f

// Device-global scratch (no allocations allowed in kernel_launch)
__device__ int    g_counts[Cn];
__device__ float  g_mlist[Cn];
__device__ double g_acc;

// ---------------------------------------------------------------------------
// Kernel 1: zero the scratch state (must be deterministic per call)
// ---------------------------------------------------------------------------
__global__ void ldam_zero_kernel() {
    int t = threadIdx.x;
    if (t < Cn) g_counts[t] = 0;
    if (t == 0) g_acc = 0.0;
}

// ---------------------------------------------------------------------------
// Kernel 2: per-class pixel-count histogram.
// int4 loads; per-warp shared sub-histograms to cut ATOMS contention 8x.
// ---------------------------------------------------------------------------
__global__ void ldam_hist_kernel(const int* __restrict__ tgt) {
    __shared__ int sc[8][Cn];   // 8 warps x 21 bins
    int tid  = threadIdx.x;
    int warp = tid >> 5;

    // zero shared hist
    for (int i = tid; i < 8 * Cn; i += blockDim.x)
        ((int*)sc)[i] = 0;
    __syncthreads();

    int n4 = NPIX / 4;
    const int4* t4 = (const int4*)tgt;
    for (int i = blockIdx.x * blockDim.x + tid; i < n4; i += gridDim.x * blockDim.x) {
        int4 v = t4[i];
        atomicAdd(&sc[warp][v.x], 1);
        atomicAdd(&sc[warp][v.y], 1);
        atomicAdd(&sc[warp][v.z], 1);
        atomicAdd(&sc[warp][v.w], 1);
    }
    __syncthreads();

    if (tid < Cn) {
        int s = 0;
#pragma unroll
        for (int w = 0; w < 8; w++) s += sc[w][tid];
        if (s) atomicAdd(&g_counts[tid], s);
    }
}

// ---------------------------------------------------------------------------
// Kernel 3: m_list = 1/(counts+1e-4)^(1/4), scaled so max(m_list) == MAX_M.
// Single warp.
// ---------------------------------------------------------------------------
__global__ void ldam_mlist_kernel() {
    int t = threadIdx.x;
    float raw = 0.0f;
    float mx  = -1e30f;
    if (t < Cn) {
        float cnt = (float)g_counts[t] + 1e-4f;
        raw = rsqrtf(sqrtf(cnt));   // (cnt)^(-1/4)
        mx  = raw;
    }
#pragma unroll
    for (int off = 16; off; off >>= 1)
        mx = fmaxf(mx, __shfl_xor_sync(0xffffffffu, mx, off));
    if (t < Cn)
        g_mlist[t] = raw * (LDAM_MAX_M / mx);
}

// ---------------------------------------------------------------------------
// Kernel 4: main LDAM loss. One thread per pixel.
// pred layout [B, C, H, W]: channel stride = HWn, so adjacent threads
// (adjacent w) make perfectly coalesced 128B loads per channel.
// All 21 logits held in registers via fully-unrolled loop; z[label] captured
// with a predicated select (no dynamic register-array indexing -> no spills).
// ---------------------------------------------------------------------------
__global__ void __launch_bounds__(256) ldam_loss_kernel(
    const float* __restrict__ pred,
    const int*   __restrict__ tgt)
{
    int p = blockIdx.x * blockDim.x + threadIdx.x;   // grid sized exactly NPIX

    int b  = p / HWn;
    int hw = p - b * HWn;
    int l  = tgt[p];
    float marg = LDAM_S * g_mlist[l];

    const float* base = pred + (size_t)b * Cn * HWn + hw;

    float z[Cn];
    float mx = -1e30f;
    float zl = 0.0f;
#pragma unroll
    for (int c = 0; c < Cn; c++) {
        float v = LDAM_S * __ldg(base + (size_t)c * HWn);
        if (c == l) v -= marg;          // predicated FADD, branch-free after unroll
        z[c] = v;
        if (c == l) zl = v;
        mx = fmaxf(mx, v);
    }

    float sum = 0.0f;
#pragma unroll
    for (int c = 0; c < Cn; c++)
        sum += __expf(z[c] - mx);       // MUFU.EX2 path

    float nll = (mx + __logf(sum)) - zl;

    // ---- block reduction: warp shuffle + shared, one double atomic/block ----
#pragma unroll
    for (int off = 16; off; off >>= 1)
        nll += __shfl_down_sync(0xffffffffu, nll, off);

    __shared__ float ws[8];
    int lane = threadIdx.x & 31;
    int warp = threadIdx.x >> 5;
    if (lane == 0) ws[warp] = nll;
    __syncthreads();

    if (threadIdx.x < 8) {
        float v = ws[threadIdx.x];
#pragma unroll
        for (int off = 4; off; off >>= 1)
            v += __shfl_down_sync(0x000000ffu, v, off);
        if (threadIdx.x == 0)
            atomicAdd(&g_acc, (double)v);
    }
}

// ---------------------------------------------------------------------------
// Kernel 5: finalize — mean over all pixels
// ---------------------------------------------------------------------------
__global__ void ldam_final_kernel(float* __restrict__ out) {
    out[0] = (float)(g_acc / (double)NPIX);
}

// ---------------------------------------------------------------------------
extern "C" void kernel_launch(void* const* d_in, const int* in_sizes, int n_in,
                              void* d_out, int out_size) {
    const float* pred = (const float*)d_in[0];
    const int*   tgt  = (const int*)d_in[1];
    float*       out  = (float*)d_out;

    ldam_zero_kernel <<<1, 32>>>();
    ldam_hist_kernel <<<1024, 256>>>(tgt);
    ldam_mlist_kernel<<<1, 32>>>();
    ldam_loss_kernel <<<NPIX / 256, 256>>>(pred, tgt);
    ldam_final_kernel<<<1, 1>>>(out);
}

// round 8
// speedup vs baseline: 1.0276x; 1.0276x over previous
#include <cuda_runtime.h>
#include <cuda_bf16.h>

#define Bsz 8
#define Cn  21
#define Hh  512
#define Ww  512
#define HWn (Hh * Ww)            // 262144
#define NPIX (Bsz * HWn)         // 2097152
#define LDAM_MAX_M 0.5f
#define LDAM_S     30.0f

// Device-global scratch (no allocations allowed in kernel_launch)
__device__ int    g_counts[Cn];
__device__ float  g_mlist[Cn];
__device__ double g_acc;

// ---------------------------------------------------------------------------
// Kernel 1: zero the scratch state (must be deterministic per call)
// ---------------------------------------------------------------------------
__global__ void ldam_zero_kernel() {
    int t = threadIdx.x;
    if (t < Cn) g_counts[t] = 0;
    if (t == 0) g_acc = 0.0;
}

// ---------------------------------------------------------------------------
// Kernel 2: per-class pixel-count histogram.
// int4 loads; per-warp shared sub-histograms to cut ATOMS contention 8x.
// ---------------------------------------------------------------------------
__global__ void ldam_hist_kernel(const int* __restrict__ tgt) {
    __shared__ int sc[8][Cn];   // 8 warps x 21 bins
    int tid  = threadIdx.x;
    int warp = tid >> 5;

    // zero shared hist
    for (int i = tid; i < 8 * Cn; i += blockDim.x)
        ((int*)sc)[i] = 0;
    __syncthreads();

    int n4 = NPIX / 4;
    const int4* t4 = (const int4*)tgt;
    for (int i = blockIdx.x * blockDim.x + tid; i < n4; i += gridDim.x * blockDim.x) {
        int4 v = t4[i];
        atomicAdd(&sc[warp][v.x], 1);
        atomicAdd(&sc[warp][v.y], 1);
        atomicAdd(&sc[warp][v.z], 1);
        atomicAdd(&sc[warp][v.w], 1);
    }
    __syncthreads();

    if (tid < Cn) {
        int s = 0;
#pragma unroll
        for (int w = 0; w < 8; w++) s += sc[w][tid];
        if (s) atomicAdd(&g_counts[tid], s);
    }
}

// ---------------------------------------------------------------------------
// Kernel 3: m_list = 1/(counts+1e-4)^(1/4), scaled so max(m_list) == MAX_M.
// Single warp.
// ---------------------------------------------------------------------------
__global__ void ldam_mlist_kernel() {
    int t = threadIdx.x;
    float raw = 0.0f;
    float mx  = -1e30f;
    if (t < Cn) {
        float cnt = (float)g_counts[t] + 1e-4f;
        raw = rsqrtf(sqrtf(cnt));   // (cnt)^(-1/4)
        mx  = raw;
    }
#pragma unroll
    for (int off = 16; off; off >>= 1)
        mx = fmaxf(mx, __shfl_xor_sync(0xffffffffu, mx, off));
    if (t < Cn)
        g_mlist[t] = raw * (LDAM_MAX_M / mx);
}

// ---------------------------------------------------------------------------
// Kernel 4: main LDAM loss. One thread per pixel.
// pred layout [B, C, H, W]: channel stride = HWn, so adjacent threads
// (adjacent w) make perfectly coalesced 128B loads per channel.
// All 21 logits held in registers via fully-unrolled loop; z[label] captured
// with a predicated select (no dynamic register-array indexing -> no spills).
// ---------------------------------------------------------------------------
__global__ void __launch_bounds__(256) ldam_loss_kernel(
    const float* __restrict__ pred,
    const int*   __restrict__ tgt)
{
    int p = blockIdx.x * blockDim.x + threadIdx.x;   // grid sized exactly NPIX

    int b  = p / HWn;
    int hw = p - b * HWn;
    int l  = tgt[p];
    float marg = LDAM_S * g_mlist[l];

    const float* base = pred + (size_t)b * Cn * HWn + hw;

    float z[Cn];
    float mx = -1e30f;
    float zl = 0.0f;
#pragma unroll
    for (int c = 0; c < Cn; c++) {
        float v = LDAM_S * __ldg(base + (size_t)c * HWn);
        if (c == l) v -= marg;          // predicated FADD, branch-free after unroll
        z[c] = v;
        if (c == l) zl = v;
        mx = fmaxf(mx, v);
    }

    float sum = 0.0f;
#pragma unroll
    for (int c = 0; c < Cn; c++)
        sum += __expf(z[c] - mx);       // MUFU.EX2 path

    float nll = (mx + __logf(sum)) - zl;

    // ---- block reduction: warp shuffle + shared, one double atomic/block ----
#pragma unroll
    for (int off = 16; off; off >>= 1)
        nll += __shfl_down_sync(0xffffffffu, nll, off);

    __shared__ float ws[8];
    int lane = threadIdx.x & 31;
    int warp = threadIdx.x >> 5;
    if (lane == 0) ws[warp] = nll;
    __syncthreads();

    if (threadIdx.x < 8) {
        float v = ws[threadIdx.x];
#pragma unroll
        for (int off = 4; off; off >>= 1)
            v += __shfl_down_sync(0x000000ffu, v, off);
        if (threadIdx.x == 0)
            atomicAdd(&g_acc, (double)v);
    }
}

// ---------------------------------------------------------------------------
// Kernel 5: finalize — mean over all pixels
// ---------------------------------------------------------------------------
__global__ void ldam_final_kernel(float* __restrict__ out) {
    out[0] = (float)(g_acc / (double)NPIX);
}

// ---------------------------------------------------------------------------
extern "C" void kernel_launch(void* const* d_in, const int* in_sizes, int n_in,
                              void* d_out, int out_size) {
    const float* pred = (const float*)d_in[0];
    const int*   tgt  = (const int*)d_in[1];
    float*       out  = (float*)d_out;

    ldam_zero_kernel <<<1, 32>>>();
    ldam_hist_kernel <<<1024, 256>>>(tgt);
    ldam_mlist_kernel<<<1, 32>>>();
    ldam_loss_kernel <<<NPIX / 256, 256>>>(pred, tgt);
    ldam_final_kernel<<<1, 1>>>(out);
}